// round 1
// baseline (speedup 1.0000x reference)
#include <cuda_runtime.h>
#include <cstdint>

// Intermediate T[l][m][n][i*4+j]  : (128, 56, 56, 8) floats = 12.85 MB scratch
__device__ float g_T[128 * 56 * 56 * 8];

#define HW 3136  // 56*56

// ---------------------------------------------------------------------------
// K1: stage 1.  out T[l,m,w, i*4+j] = sum_{kk<64, tap<3} x[l, 2kk+i, hsrc, w] * w1[kk,tap,j]
//   hsrc = (m+tap-2) mod 56, contribution zero when (m+tap-1) outside [0,56)
// Block: 224 threads = cg(4) x wq(14) x m(4).  Grid: (14 m-chunks, 128 l)
// ---------------------------------------------------------------------------
__global__ __launch_bounds__(224) void k1_stage1(const float* __restrict__ x,
                                                 const float* __restrict__ w1) {
    __shared__ float4 w1s[64 * 3];   // [kk*3 + tap] -> (j0..j3)

    int tid = threadIdx.x;
    if (tid < 192) w1s[tid] = reinterpret_cast<const float4*>(w1)[tid];
    __syncthreads();

    int cg = tid & 3;            // channel group (16 kk each)
    int wq = (tid >> 2) % 14;    // w quad
    int m  = tid / 56;           // local m (0..3)
    int l  = blockIdx.y;
    int mg = blockIdx.x * 4 + m; // global m
    int w0 = wq * 4;

    // per-tap source rows + validity
    int  rows[3];
    bool val[3];
#pragma unroll
    for (int tap = 0; tap < 3; tap++) {
        int hp = mg + tap - 1;                  // unfold position
        val[tap]  = (hp >= 0) && (hp < 56);
        rows[tap] = (hp <= 0) ? 55 : hp - 1;    // roll(+1): (hp-1) mod 56
    }

    float acc[2][4][4];  // [i][j][ww]
#pragma unroll
    for (int i = 0; i < 2; i++)
#pragma unroll
        for (int j = 0; j < 4; j++)
#pragma unroll
            for (int ww = 0; ww < 4; ww++) acc[i][j][ww] = 0.0f;

    const float* xb = x + (size_t)l * 128 * HW;

#pragma unroll 4
    for (int kl = 0; kl < 16; kl++) {
        int kk = cg * 16 + kl;
#pragma unroll
        for (int tap = 0; tap < 3; tap++) {
            if (val[tap]) {
                float4 wv = w1s[kk * 3 + tap];
                float wj[4] = {wv.x, wv.y, wv.z, wv.w};
#pragma unroll
                for (int i = 0; i < 2; i++) {
                    int c = 2 * kk + i;
                    float4 xv = *reinterpret_cast<const float4*>(
                        xb + c * HW + rows[tap] * 56 + w0);
                    float xw[4] = {xv.x, xv.y, xv.z, xv.w};
#pragma unroll
                    for (int j = 0; j < 4; j++)
#pragma unroll
                        for (int ww = 0; ww < 4; ww++)
                            acc[i][j][ww] += xw[ww] * wj[j];
                }
            }
        }
    }

    // reduce the 4 channel groups: partners are lanes (tid ^ 1), (tid ^ 2)
#pragma unroll
    for (int i = 0; i < 2; i++)
#pragma unroll
        for (int j = 0; j < 4; j++)
#pragma unroll
            for (int ww = 0; ww < 4; ww++) {
                float v = acc[i][j][ww];
                v += __shfl_xor_sync(0xffffffffu, v, 1);
                v += __shfl_xor_sync(0xffffffffu, v, 2);
                acc[i][j][ww] = v;
            }

    if (cg == 0) {
        float* Tp = g_T + (((size_t)l * 56 + mg) * 56 + w0) * 8;
#pragma unroll
        for (int ww = 0; ww < 4; ww++) {
            float4 a = make_float4(acc[0][0][ww], acc[0][1][ww], acc[0][2][ww], acc[0][3][ww]);
            float4 b = make_float4(acc[1][0][ww], acc[1][1][ww], acc[1][2][ww], acc[1][3][ww]);
            *reinterpret_cast<float4*>(Tp + ww * 8)     = a;
            *reinterpret_cast<float4*>(Tp + ww * 8 + 4) = b;
        }
    }
}

// ---------------------------------------------------------------------------
// K2: stage 2.  out[l, 4j+oo, m, n] = sum_{i<2,k<3} T[l,m,n+k-1, i*4+oo] * w2[i,k,j]
// Thread = (l, m, nq) covering n = 4nq..4nq+3 and all 128 output channels.
// Total items: 128*56*14 = 100352 = 392 blocks * 256 threads (exact).
// ---------------------------------------------------------------------------
__global__ __launch_bounds__(256) void k2_stage2(const float* __restrict__ w2,
                                                 float* __restrict__ out) {
    __shared__ float w2s[192];   // [i*96 + k*32 + j]
    int tid = threadIdx.x;
    if (tid < 192) w2s[tid] = w2[tid];
    __syncthreads();

    int gt  = blockIdx.x * 256 + tid;
    int nq  = gt % 14;
    int rem = gt / 14;
    int m   = rem % 56;
    int l   = rem / 56;

    // load 6 T positions: n' = 4nq-1 .. 4nq+4
    float tv[6][8];
    const float* Tp = g_T + (((size_t)l * 56 + m) * 56) * 8;
#pragma unroll
    for (int s = 0; s < 6; s++) {
        int np = 4 * nq - 1 + s;
        if (np >= 0 && np < 56) {
            float4 a = *reinterpret_cast<const float4*>(Tp + np * 8);
            float4 b = *reinterpret_cast<const float4*>(Tp + np * 8 + 4);
            tv[s][0] = a.x; tv[s][1] = a.y; tv[s][2] = a.z; tv[s][3] = a.w;
            tv[s][4] = b.x; tv[s][5] = b.y; tv[s][6] = b.z; tv[s][7] = b.w;
        } else {
#pragma unroll
            for (int t = 0; t < 8; t++) tv[s][t] = 0.0f;
        }
    }

    float* ob = out + (size_t)l * 128 * HW + m * 56 + 4 * nq;

#pragma unroll 4
    for (int j = 0; j < 32; j++) {
        float wv[6];
#pragma unroll
        for (int i2 = 0; i2 < 2; i2++)
#pragma unroll
            for (int k = 0; k < 3; k++)
                wv[i2 * 3 + k] = w2s[i2 * 96 + k * 32 + j];

#pragma unroll
        for (int oo = 0; oo < 4; oo++) {
            float rr[4];
#pragma unroll
            for (int nn = 0; nn < 4; nn++) {
                float s = 0.0f;
#pragma unroll
                for (int i2 = 0; i2 < 2; i2++)
#pragma unroll
                    for (int k = 0; k < 3; k++)
                        s += tv[nn + k][i2 * 4 + oo] * wv[i2 * 3 + k];
                rr[nn] = s;
            }
            *reinterpret_cast<float4*>(ob + (size_t)(4 * j + oo) * HW) =
                make_float4(rr[0], rr[1], rr[2], rr[3]);
        }
    }
}

// ---------------------------------------------------------------------------
extern "C" void kernel_launch(void* const* d_in, const int* in_sizes, int n_in,
                              void* d_out, int out_size) {
    const float* x  = nullptr;
    const float* w1 = nullptr;
    const float* w2 = nullptr;
    for (int i = 0; i < n_in; i++) {
        if (in_sizes[i] == 128 * 128 * 56 * 56) x  = (const float*)d_in[i];
        else if (in_sizes[i] == 64 * 3 * 4)     w1 = (const float*)d_in[i];
        else if (in_sizes[i] == 2 * 3 * 32)     w2 = (const float*)d_in[i];
    }
    // fallback to positional order
    if (!x)  x  = (const float*)d_in[0];
    if (!w1) w1 = (const float*)d_in[1];
    if (!w2) w2 = (const float*)d_in[2];

    k1_stage1<<<dim3(14, 128), 224>>>(x, w1);
    k2_stage2<<<392, 256>>>(w2, (float*)d_out);
}